// round 2
// baseline (speedup 1.0000x reference)
#include <cuda_runtime.h>
#include <math.h>

// Problem constants: B=4, N=2048, M=64, L=64
// inputs (metadata order):
//  0: targets_receptor (B,N,L)      = 524288 f32
//  1: neighbors_ligand (B,N,M,L)    = 33554432 f32   <-- dominant stream
//  2: a                (B,N,M)      = 524288 f32
//  3: kernel_l (1,1,L) = 64 f32
//  4: bias_l   (1,1,L) = 64 f32
//  5: kernel_r (1,1,L) = 64 f32
//  6: bias_r   (1,1,L) = 64 f32
// output: (B,N,L) f32, sigmoid( (kr*r+br) * (kl*S1 + bl*S0) )
//   S1[l] = sum_m lig[m,l]*a[m],  S0 = sum_m a[m]

#define PAIRS_PER_BLOCK 16
#define THREADS (PAIRS_PER_BLOCK * 16)
#define NUM_PAIRS (4 * 2048)

__global__ __launch_bounds__(THREADS)
void single_lr_gat_kernel(const float* __restrict__ r,
                          const float* __restrict__ lig,
                          const float* __restrict__ a,
                          const float* __restrict__ kl,
                          const float* __restrict__ bl,
                          const float* __restrict__ kr,
                          const float* __restrict__ br,
                          float* __restrict__ out) {
    const int q = threadIdx.x & 15;   // quad index along L: covers l = 4q..4q+3
    const int p = threadIdx.x >> 4;   // pair slot within block
    const int pair = blockIdx.x * PAIRS_PER_BLOCK + p;   // (b*N + n), grid is exact

    __shared__ float a_sh[PAIRS_PER_BLOCK][64];

    // Stage a[pair, 0:64] into shared: each 16-lane group loads its own pair's a
    // with one float4 per lane (fully coalesced per pair: 256B).
    {
        const float4 av = reinterpret_cast<const float4*>(a + (size_t)pair * 64)[q];
        a_sh[p][q * 4 + 0] = av.x;
        a_sh[p][q * 4 + 1] = av.y;
        a_sh[p][q * 4 + 2] = av.z;
        a_sh[p][q * 4 + 3] = av.w;
    }
    __syncthreads();

    // Stream the 64x64 ligand tile for this pair, accumulating
    // S1[l] (4 lanes' worth) and S0 (redundant per lane, cheap).
    const float4* __restrict__ lig4 =
        reinterpret_cast<const float4*>(lig + (size_t)pair * 64 * 64);

    float4 s1 = make_float4(0.f, 0.f, 0.f, 0.f);
    float s0 = 0.f;

#pragma unroll 8
    for (int m = 0; m < 64; ++m) {
        const float4 v = lig4[m * 16 + q];
        const float am = a_sh[p][m];
        s1.x = fmaf(v.x, am, s1.x);
        s1.y = fmaf(v.y, am, s1.y);
        s1.z = fmaf(v.z, am, s1.z);
        s1.w = fmaf(v.w, am, s1.w);
        s0 += am;
    }

    // Epilogue: small per-L params + receptor row, then sigmoid.
    const float4 kl4 = reinterpret_cast<const float4*>(kl)[q];
    const float4 bl4 = reinterpret_cast<const float4*>(bl)[q];
    const float4 kr4 = reinterpret_cast<const float4*>(kr)[q];
    const float4 br4 = reinterpret_cast<const float4*>(br)[q];
    const float4 rv  = reinterpret_cast<const float4*>(r + (size_t)pair * 64)[q];

    float4 w;
    w.x = fmaf(kr4.x, rv.x, br4.x) * fmaf(kl4.x, s1.x, bl4.x * s0);
    w.y = fmaf(kr4.y, rv.y, br4.y) * fmaf(kl4.y, s1.y, bl4.y * s0);
    w.z = fmaf(kr4.z, rv.z, br4.z) * fmaf(kl4.z, s1.z, bl4.z * s0);
    w.w = fmaf(kr4.w, rv.w, br4.w) * fmaf(kl4.w, s1.w, bl4.w * s0);

    float4 o;
    o.x = 1.f / (1.f + expf(-w.x));
    o.y = 1.f / (1.f + expf(-w.y));
    o.z = 1.f / (1.f + expf(-w.z));
    o.w = 1.f / (1.f + expf(-w.w));

    reinterpret_cast<float4*>(out + (size_t)pair * 64)[q] = o;
}

extern "C" void kernel_launch(void* const* d_in, const int* in_sizes, int n_in,
                              void* d_out, int out_size) {
    const float* r   = (const float*)d_in[0];
    const float* lig = (const float*)d_in[1];
    const float* a   = (const float*)d_in[2];
    const float* kl  = (const float*)d_in[3];
    const float* bl  = (const float*)d_in[4];
    const float* kr  = (const float*)d_in[5];
    const float* br  = (const float*)d_in[6];
    float* out = (float*)d_out;

    const int grid = NUM_PAIRS / PAIRS_PER_BLOCK;   // 8192/16 = 512 blocks
    single_lr_gat_kernel<<<grid, THREADS>>>(r, lig, a, kl, bl, kr, br, out);
}

// round 6
// speedup vs baseline: 1.1472x; 1.1472x over previous
#include <cuda_runtime.h>
#include <math.h>

// B=4, N=2048, M=64, L=64
// out[b,n,l] = sigmoid( (kr[l]*r[b,n,l]+br[l]) * (kl[l]*S1[l] + bl[l]*S0) )
//   S1[l] = sum_m lig[b,n,m,l]*a[b,n,m],  S0 = sum_m a[b,n,m]
//
// One WARP per (b,n) pair. lane = q + 16*mh:
//   q  in [0,16): quad along L (l = 4q..4q+3), float4 loads
//   mh in {0,1} : half of the m-dimension (32 neighbors each)
// Final shfl_xor(16) combines the two m-halves.
// 2048 blocks x 256 threads = 262144 threads -> ~55 warps/SM (~86% occ),
// doubling per-SM outstanding LDG.128 vs the previous latency-bound version.

#define PAIRS_PER_BLOCK 8
#define THREADS (PAIRS_PER_BLOCK * 32)
#define NUM_PAIRS (4 * 2048)

__global__ __launch_bounds__(THREADS)
void single_lr_gat_kernel(const float* __restrict__ r,
                          const float* __restrict__ lig,
                          const float* __restrict__ a,
                          const float* __restrict__ kl,
                          const float* __restrict__ bl,
                          const float* __restrict__ kr,
                          const float* __restrict__ br,
                          float* __restrict__ out) {
    const int lane = threadIdx.x & 31;
    const int q    = lane & 15;        // quad along L
    const int mh   = lane >> 4;        // which half of m
    const int p    = threadIdx.x >> 5; // warp (=pair slot) within block
    const int pair = blockIdx.x * PAIRS_PER_BLOCK + p;

    __shared__ float a_sh[PAIRS_PER_BLOCK][64];

    // Per-warp stage of a[pair, 0:64]: each lane loads 2 floats (coalesced 256B).
    {
        const float* ap = a + (size_t)pair * 64;
        a_sh[p][lane]      = ap[lane];
        a_sh[p][lane + 32] = ap[lane + 32];
    }
    __syncwarp();

    // Each lane streams 32 float4s: m in [mh*32, mh*32+32), fixed quad q.
    const float4* __restrict__ lig4 =
        reinterpret_cast<const float4*>(lig + (size_t)pair * 64 * 64) + mh * (32 * 16) + q;
    const float* __restrict__ arow = &a_sh[p][mh * 32];

    float4 s1 = make_float4(0.f, 0.f, 0.f, 0.f);
    float s0 = 0.f;

#pragma unroll 8
    for (int j = 0; j < 32; ++j) {
        const float4 v = lig4[j * 16];
        const float am = arow[j];
        s1.x = fmaf(v.x, am, s1.x);
        s1.y = fmaf(v.y, am, s1.y);
        s1.z = fmaf(v.z, am, s1.z);
        s1.w = fmaf(v.w, am, s1.w);
        s0 += am;
    }

    // Combine the two m-halves: lanes q and q+16 hold partial sums for the same l's.
    s1.x += __shfl_xor_sync(0xFFFFFFFF, s1.x, 16);
    s1.y += __shfl_xor_sync(0xFFFFFFFF, s1.y, 16);
    s1.z += __shfl_xor_sync(0xFFFFFFFF, s1.z, 16);
    s1.w += __shfl_xor_sync(0xFFFFFFFF, s1.w, 16);
    s0   += __shfl_xor_sync(0xFFFFFFFF, s0,   16);

    if (lane < 16) {
        const float4 kl4 = reinterpret_cast<const float4*>(kl)[q];
        const float4 bl4 = reinterpret_cast<const float4*>(bl)[q];
        const float4 kr4 = reinterpret_cast<const float4*>(kr)[q];
        const float4 br4 = reinterpret_cast<const float4*>(br)[q];
        const float4 rv  = reinterpret_cast<const float4*>(r + (size_t)pair * 64)[q];

        float4 w;
        w.x = fmaf(kr4.x, rv.x, br4.x) * fmaf(kl4.x, s1.x, bl4.x * s0);
        w.y = fmaf(kr4.y, rv.y, br4.y) * fmaf(kl4.y, s1.y, bl4.y * s0);
        w.z = fmaf(kr4.z, rv.z, br4.z) * fmaf(kl4.z, s1.z, bl4.z * s0);
        w.w = fmaf(kr4.w, rv.w, br4.w) * fmaf(kl4.w, s1.w, bl4.w * s0);

        float4 o;
        o.x = 1.f / (1.f + expf(-w.x));
        o.y = 1.f / (1.f + expf(-w.y));
        o.z = 1.f / (1.f + expf(-w.z));
        o.w = 1.f / (1.f + expf(-w.w));

        reinterpret_cast<float4*>(out + (size_t)pair * 64)[q] = o;
    }
}

extern "C" void kernel_launch(void* const* d_in, const int* in_sizes, int n_in,
                              void* d_out, int out_size) {
    const float* r   = (const float*)d_in[0];
    const float* lig = (const float*)d_in[1];
    const float* a   = (const float*)d_in[2];
    const float* kl  = (const float*)d_in[3];
    const float* bl  = (const float*)d_in[4];
    const float* kr  = (const float*)d_in[5];
    const float* br  = (const float*)d_in[6];
    float* out = (float*)d_out;

    const int grid = NUM_PAIRS / PAIRS_PER_BLOCK;   // 8192/8 = 1024 blocks
    single_lr_gat_kernel<<<grid, THREADS>>>(r, lig, a, kl, bl, kr, br, out);
}